// round 13
// baseline (speedup 1.0000x reference)
#include <cuda_runtime.h>
#include <cuda_fp16.h>
#include <math.h>
#include <stdint.h>

#define HF 100
#define WF 160
#define CIN 512
#define CC 512
#define NA 9
#define NPIX (HF*WF)
#define NANCH (NPIX*NA)      // 144000
#define PRE_NMS 6000
#define POST_NMS 300
#define NEGV -1e9f
#define IMG_H 1600.0f
#define IMG_W 2560.0f

// ---------------- device scratch (no allocations allowed) ----------------
__device__ float  g_y[NPIX*CC];                // conv output (relu'd), 32.8 MB
__device__ __half g_fm_h[NPIX*CIN];            // fp16 hi of feature map
__device__ __half g_fm_l[NPIX*CIN];            // fp16 lo*2048
__device__ __half g_w_h[9*CC*CIN];             // [tap][co][cin] hi
__device__ __half g_w_l[9*CC*CIN];             // lo*2048
__device__ float  g_hw2[512*45];               // heads weights [k][o] (o minor)
__device__ unsigned int g_hist1[65536];
__device__ unsigned int g_hist2[65536];
__device__ unsigned int g_binB, g_rank_before, g_T, g_G, g_need_eq;
__device__ unsigned int g_cnt_gt, g_eq_cnt;
__device__ unsigned long long g_pairs[8192];
__device__ unsigned int g_eq_idx[NANCH];
__device__ int   g_top_idx[PRE_NMS];
__device__ float g_top_score[PRE_NMS];
__device__ float g_by1[PRE_NMS], g_bx1[PRE_NMS], g_by2[PRE_NMS], g_bx2[PRE_NMS];
__device__ float g_nsc[PRE_NMS];

// ================= helpers =================
static __device__ __forceinline__ uint32_t smem_u32(const void* p) {
    uint32_t a;
    asm("{ .reg .u64 t; cvta.to.shared.u64 t, %1; cvt.u32.u64 %0, t; }" : "=r"(a) : "l"(p));
    return a;
}
static __device__ __forceinline__ void cpa16(uint32_t dst, const void* src, uint32_t sz) {
    asm volatile("cp.async.cg.shared.global [%0], [%1], 16, %2;" :: "r"(dst), "l"(src), "r"(sz) : "memory");
}
static __device__ __forceinline__ void cpa16f(uint32_t dst, const void* src) {
    asm volatile("cp.async.cg.shared.global [%0], [%1], 16;" :: "r"(dst), "l"(src) : "memory");
}
#define CP_COMMIT() asm volatile("cp.async.commit_group;" ::: "memory")
#define CP_WAIT2()  asm volatile("cp.async.wait_group 2;" ::: "memory")

static __device__ __forceinline__ void ldsm4(uint32_t* r, uint32_t addr) {
    asm volatile("ldmatrix.sync.aligned.m8n8.x4.shared.b16 {%0,%1,%2,%3}, [%4];"
        : "=r"(r[0]), "=r"(r[1]), "=r"(r[2]), "=r"(r[3]) : "r"(addr));
}
static __device__ __forceinline__ void mma16(float* d, const uint32_t* a, uint32_t b0, uint32_t b1) {
    asm volatile(
        "mma.sync.aligned.m16n8k16.row.col.f32.f16.f16.f32 "
        "{%0,%1,%2,%3}, {%4,%5,%6,%7}, {%8,%9}, {%0,%1,%2,%3};"
        : "+f"(d[0]), "+f"(d[1]), "+f"(d[2]), "+f"(d[3])
        : "r"(a[0]), "r"(a[1]), "r"(a[2]), "r"(a[3]), "r"(b0), "r"(b1));
}

// ================= fused packing kernel =================
// blocks [0, 32000): fm hi/lo split
// blocks [32000, 41216): W1 hi/lo split + transpose to [tap][co][cin]
// blocks [41216, 41306): heads weights
#define PACK_FM_BLKS 32000
#define PACK_W_BLKS  9216
#define PACK_HW_BLKS 90
#define PACK_TOTAL   (PACK_FM_BLKS + PACK_W_BLKS + PACK_HW_BLKS)

__global__ void fused_pack_kernel(const float* __restrict__ fm,
                                  const float* __restrict__ W1,
                                  const float* __restrict__ Wc,
                                  const float* __restrict__ Wr) {
    int b = blockIdx.x;
    if (b < PACK_FM_BLKS) {
        int i = b*256 + threadIdx.x;
        if (i < NPIX*CIN) {
            float x = fm[i];
            __half h = __float2half_rn(x);
            float  r = x - __half2float(h);
            g_fm_h[i] = h;
            g_fm_l[i] = __float2half_rn(r * 2048.0f);
        }
    } else if (b < PACK_FM_BLKS + PACK_W_BLKS) {
        int i = (b - PACK_FM_BLKS)*256 + threadIdx.x;
        if (i < 9*CIN*CC) {
            int tap = i / (CIN*CC), rem = i - tap*(CIN*CC);
            int cin = rem >> 9, co = rem & 511;           // W1 is [tap][cin][co]
            float x = W1[i];
            __half h = __float2half_rn(x);
            float  r = x - __half2float(h);
            size_t dst = ((size_t)tap*CC + co)*CIN + cin; // [tap][co][cin]
            g_w_h[dst] = h;
            g_w_l[dst] = __float2half_rn(r * 2048.0f);
        }
    } else {
        int i = (b - PACK_FM_BLKS - PACK_W_BLKS)*256 + threadIdx.x;
        if (i < 512*45) {
            int k = i / 45, o = i - k*45;
            g_hw2[i] = (o < 9) ? Wc[k*9 + o] : Wr[k*36 + (o-9)];
        }
    }
}

// ================= conv 3x3 512->512 via mma.sync fp16 (3-term split) =================
// R6 tiling (8x16 px x 64 co, ROWB=48, K=16/iter), paired iterations (R10): 144 super-iters.
#define ROWB  48
#define SEG_A (180*ROWB)       // 8640 (one of hi/lo)
#define ABUF  (2*SEG_A)        // 17280
#define SEG_B (64*ROWB)        // 3072
#define BSTG  (2*SEG_B)        // 6144
#define BOFF  (2*ABUF)         // 34560
#define NBSTG 6
#define CONV_SMEM (BOFF + NBSTG*BSTG)   // 71424 B

__global__ __launch_bounds__(256, 2) void conv_mma_kernel(const float* __restrict__ b1) {
    extern __shared__ char smraw[];
    uint32_t sb = smem_u32(smraw);
    int t = threadIdx.x;
    int row0 = blockIdx.y * 8;
    int col0 = blockIdx.x * 16;
    int n0   = blockIdx.z * 64;
    int wid = t >> 5, lane = t & 31;
    int g = lane >> 2, tg = lane & 3;
    int wm = wid >> 1, wn = wid & 1;
    int r8 = lane & 7, sel = lane >> 3;

    uint32_t aOff[2];
    {
        int apix = r8 + ((sel & 1) ? 8 : 0);
        int akb  = (sel & 2) ? 16 : 0;
        #pragma unroll
        for (int mt = 0; mt < 2; mt++)
            aOff[mt] = (uint32_t)(((2*wm + mt)*18 + apix)*ROWB + akb);
    }
    uint32_t bOff[2];
    {
        int bco = r8 + ((sel & 2) ? 8 : 0);
        int bkb = (sel & 1) ? 16 : 0;
        #pragma unroll
        for (int q = 0; q < 2; q++)
            bOff[q] = (uint32_t)((wn*32 + q*16 + bco)*ROWB + bkb);
    }

    float accD[2][4][4], accE[2][4][4];
    #pragma unroll
    for (int mt = 0; mt < 2; mt++)
        #pragma unroll
        for (int nt = 0; nt < 4; nt++)
            #pragma unroll
            for (int v = 0; v < 4; v++) { accD[mt][nt][v] = 0.f; accE[mt][nt][v] = 0.f; }

    auto loadA = [&](int buf, int cc) {
        uint32_t Ab = sb + buf*ABUF;
        #pragma unroll 1
        for (int o = t; o < 720; o += 256) {
            int pix = o >> 2, part = o & 3;
            int seg = part >> 1, hh = part & 1;
            int hr = pix / 18, hc = pix - hr*18;
            int gr = row0 - 1 + hr, gc = col0 - 1 + hc;
            bool v = ((unsigned)gr < (unsigned)HF) && ((unsigned)gc < (unsigned)WF);
            const __half* base = seg ? g_fm_l : g_fm_h;
            const __half* src = v ? (base + (size_t)(gr*WF + gc)*CIN + cc*16 + hh*8) : base;
            cpa16(Ab + (uint32_t)(seg*SEG_A + pix*ROWB + hh*16), src, v ? 16u : 0u);
        }
    };
    auto loadB = [&](int buf, int tap, int cc) {
        uint32_t Bb = sb + BOFF + buf*BSTG;
        int co = t >> 2, part = t & 3;
        int seg = part >> 1, hh = part & 1;
        const __half* base = seg ? g_w_l : g_w_h;
        cpa16f(Bb + (uint32_t)(seg*SEG_B + co*ROWB + hh*16),
               base + ((size_t)tap*CC + n0 + co)*CIN + cc*16 + hh*8);
    };

    auto compute_iter = [&](int j) {
        int cc = j / 9, tap = j - cc*9;
        uint32_t tapAdd = (uint32_t)(((tap/3)*18 + (tap%3))*ROWB);
        uint32_t Ab = sb + (cc & 1)*ABUF + tapAdd;
        uint32_t Bb = sb + BOFF + (j % NBSTG)*BSTG;

        uint32_t a_h[2][4], a_l[2][4], b_h[2][4], b_l[2][4];
        #pragma unroll
        for (int mt = 0; mt < 2; mt++) {
            ldsm4(a_h[mt], Ab + aOff[mt]);
            ldsm4(a_l[mt], Ab + SEG_A + aOff[mt]);
        }
        #pragma unroll
        for (int q = 0; q < 2; q++) {
            ldsm4(b_h[q], Bb + bOff[q]);
            ldsm4(b_l[q], Bb + SEG_B + bOff[q]);
        }
        #pragma unroll
        for (int mt = 0; mt < 2; mt++)
            #pragma unroll
            for (int nt = 0; nt < 4; nt++) {
                int q = nt >> 1, h2 = (nt & 1)*2;
                mma16(accD[mt][nt], a_h[mt], b_h[q][h2], b_h[q][h2+1]);
                mma16(accE[mt][nt], a_l[mt], b_h[q][h2], b_h[q][h2+1]);
                mma16(accE[mt][nt], a_h[mt], b_l[q][h2], b_l[q][h2+1]);
            }
    };

    loadA(0, 0);
    loadB(0, 0, 0); CP_COMMIT();
    loadB(1, 1, 0); CP_COMMIT();
    loadB(2, 2, 0); CP_COMMIT();
    loadB(3, 3, 0); CP_COMMIT();

    for (int s = 0; s < 144; s++) {
        CP_WAIT2();
        __syncthreads();
        #pragma unroll
        for (int e = 0; e < 2; e++) {
            int j = 2*s + 4 + e;
            if (j < 288) {
                int ncc = j / 9, ntap = j - ncc*9;
                if (ntap == 0) loadA(ncc & 1, ncc);
                loadB(j % NBSTG, ntap, ncc);
            }
            CP_COMMIT();
        }
        compute_iter(2*s);
        compute_iter(2*s + 1);
    }

    const float INV2048 = 1.0f/2048.0f;
    #pragma unroll
    for (int mt = 0; mt < 2; mt++) {
        int gr = row0 + 2*wm + mt;
        if (gr < HF) {
            int pixA = gr*WF + col0 + g;
            int pixB = pixA + 8;
            #pragma unroll
            for (int nt = 0; nt < 4; nt++) {
                int col = n0 + wn*32 + nt*8 + 2*tg;
                float bb0 = b1[col], bb1 = b1[col + 1];
                float2 oA, oB;
                oA.x = fmaxf(accD[mt][nt][0] + accE[mt][nt][0]*INV2048 + bb0, 0.f);
                oA.y = fmaxf(accD[mt][nt][1] + accE[mt][nt][1]*INV2048 + bb1, 0.f);
                oB.x = fmaxf(accD[mt][nt][2] + accE[mt][nt][2]*INV2048 + bb0, 0.f);
                oB.y = fmaxf(accD[mt][nt][3] + accE[mt][nt][3]*INV2048 + bb1, 0.f);
                *reinterpret_cast<float2*>(g_y + (size_t)pixA*512 + col) = oA;
                *reinterpret_cast<float2*>(g_y + (size_t)pixB*512 + col) = oB;
            }
        }
    }
}

// ---------------- 1x1 heads + softmax(9) + deltas + fused hist1 ----------------
__global__ __launch_bounds__(384) void heads_kernel(const float* __restrict__ bc,
                                                    const float* __restrict__ br,
                                                    float* __restrict__ out) {
    __shared__ float ys[8*128];
    __shared__ float ws[128*45];
    __shared__ float lg[8][9];

    int t  = threadIdx.x;
    int p0 = blockIdx.x * 8;
    int pp = t / 45, o = t - pp*45;

    float acc = 0.f;
    for (int c0 = 0; c0 < 512; c0 += 128) {
        __syncthreads();
        for (int idx = t; idx < 256; idx += 384) {
            int pix = idx >> 5, v = idx & 31;
            *reinterpret_cast<float4*>(ys + pix*128 + v*4) =
                *reinterpret_cast<const float4*>(g_y + (size_t)(p0+pix)*512 + c0 + v*4);
        }
        {
            float4* ws4 = reinterpret_cast<float4*>(ws);
            const float4* gw4 = reinterpret_cast<const float4*>(g_hw2 + c0*45);
            for (int i = t; i < 1440; i += 384) ws4[i] = gw4[i];
        }
        __syncthreads();
        if (t < 360) {
            const float4* yv = reinterpret_cast<const float4*>(ys + pp*128);
            #pragma unroll 8
            for (int k4 = 0; k4 < 32; k4++) {
                float4 y4 = yv[k4];
                acc = fmaf(y4.x, ws[(k4*4+0)*45+o], acc);
                acc = fmaf(y4.y, ws[(k4*4+1)*45+o], acc);
                acc = fmaf(y4.z, ws[(k4*4+2)*45+o], acc);
                acc = fmaf(y4.w, ws[(k4*4+3)*45+o], acc);
            }
        }
    }

    if (t < 360) {
        int gp = p0 + pp;
        if (o < 9) lg[pp][o] = acc + bc[o];
        else       out[NANCH + (size_t)gp*36 + (o-9)] = acc + br[o-9];
    }
    __syncthreads();
    if (t < 360 && o < 9) {
        int gp = p0 + pp;
        float m = lg[pp][0];
        #pragma unroll
        for (int j = 1; j < 9; j++) m = fmaxf(m, lg[pp][j]);
        float sum = 0.f;
        #pragma unroll
        for (int j = 0; j < 9; j++) sum += expf(lg[pp][j]-m);
        float sc = expf(lg[pp][o]-m)/sum;
        out[(size_t)gp*9 + o] = sc;
        atomicAdd(&g_hist1[__float_as_uint(sc) >> 16], 1u);
    }
}

// ---------------- exact top-k(6000) via 2-level radix ----------------
__global__ void zero_kernel() {
    int i = blockIdx.x*blockDim.x + threadIdx.x;
    if (i < 65536) g_hist1[i] = 0u;
    else if (i < 131072) g_hist2[i-65536] = 0u;
    else if (i == 131072) { g_cnt_gt = 0u; g_eq_cnt = 0u; }
}

__global__ void find_bin1_kernel() {
    __shared__ unsigned csum[1024];
    int t = threadIdx.x;
    unsigned s = 0;
    for (int b = 0; b < 64; b++) s += g_hist1[t*64+b];
    csum[t] = s;
    __syncthreads();
    if (t == 0) {
        unsigned cum = 0; int chunk = 0;
        for (int q = 1023; q >= 0; q--) {
            if (cum + csum[q] >= (unsigned)PRE_NMS) { chunk = q; break; }
            cum += csum[q];
        }
        unsigned B = 0;
        for (int b = chunk*64+63; b >= chunk*64; b--) {
            unsigned h = g_hist1[b];
            if (cum + h >= (unsigned)PRE_NMS) { B = (unsigned)b; break; }
            cum += h;
        }
        g_binB = B; g_rank_before = cum;
    }
}

__global__ void hist2_kernel(const float* __restrict__ out) {
    int i = blockIdx.x*blockDim.x + threadIdx.x;
    unsigned u = 0; bool p = false;
    if (i < NANCH) {
        u = __float_as_uint(out[i]);
        p = (u >> 16) == g_binB;
    }
    unsigned amask = __ballot_sync(0xffffffffu, p);
    if (p) {
        unsigned low = u & 0xFFFFu;
        unsigned m = __match_any_sync(amask, low);
        if ((int)(threadIdx.x & 31) == __ffs(m) - 1)
            atomicAdd(&g_hist2[low], (unsigned)__popc(m));
    }
}

__global__ void find_thresh_kernel() {
    __shared__ unsigned csum[1024];
    int t = threadIdx.x;
    unsigned s = 0;
    for (int b = 0; b < 64; b++) s += g_hist2[t*64+b];
    csum[t] = s;
    __syncthreads();
    if (t == 0) {
        unsigned cum = g_rank_before; int chunk = 0;
        for (int q = 1023; q >= 0; q--) {
            if (cum + csum[q] >= (unsigned)PRE_NMS) { chunk = q; break; }
            cum += csum[q];
        }
        unsigned L = 0;
        for (int b = chunk*64+63; b >= chunk*64; b--) {
            unsigned h = g_hist2[b];
            if (cum + h >= (unsigned)PRE_NMS) { L = (unsigned)b; break; }
            cum += h;
        }
        g_T = (g_binB << 16) | L;
        g_G = cum;
        g_need_eq = (unsigned)PRE_NMS - cum;
    }
}

__global__ void compact_kernel(const float* __restrict__ out) {
    int i = blockIdx.x*blockDim.x + threadIdx.x;
    if (i < NANCH) {
        unsigned u = __float_as_uint(out[i]);
        unsigned T = g_T;
        if (u > T) {
            unsigned pos = atomicAdd(&g_cnt_gt, 1u);
            g_pairs[pos] = (((unsigned long long)u) << 32) | (unsigned)(~(unsigned)i);
        } else if (u == T) {
            unsigned pos = atomicAdd(&g_eq_cnt, 1u);
            g_eq_idx[pos] = (unsigned)i;
        }
    }
}

__global__ void eq_rank_kernel() {
    unsigned E = g_eq_cnt, need = g_need_eq, G = g_G, T = g_T;
    for (unsigned e = blockIdx.x*blockDim.x + threadIdx.x; e < E; e += gridDim.x*blockDim.x) {
        unsigned idx = g_eq_idx[e];
        unsigned rank = 0;
        for (unsigned f = 0; f < E; f++) rank += (g_eq_idx[f] < idx) ? 1u : 0u;
        if (rank < need)
            g_pairs[G + rank] = (((unsigned long long)T) << 32) | (unsigned)(~idx);
    }
}

__global__ void sort_kernel() {
    extern __shared__ unsigned long long sk[];
    int t = threadIdx.x;
    for (int j = t; j < 8192; j += 1024) sk[j] = (j < PRE_NMS) ? g_pairs[j] : 0ULL;
    __syncthreads();
    for (int k = 2; k <= 8192; k <<= 1) {
        for (int j = k >> 1; j > 0; j >>= 1) {
            for (int idx = t; idx < 8192; idx += 1024) {
                int ixj = idx ^ j;
                if (ixj > idx) {
                    unsigned long long a = sk[idx], b = sk[ixj];
                    bool desc = (idx & k) == 0;
                    if (desc ? (a < b) : (a > b)) { sk[idx] = b; sk[ixj] = a; }
                }
            }
            __syncthreads();
        }
    }
    for (int j = t; j < PRE_NMS; j += 1024) {
        unsigned long long p = sk[j];
        unsigned u = (unsigned)(p >> 32);
        unsigned idx = ~((unsigned)p);
        g_top_idx[j] = (int)idx;
        g_top_score[j] = __uint_as_float(u);
    }
}

__global__ void decode_kernel(const float* __restrict__ amap, const float* __restrict__ out) {
    int j = blockIdx.x*blockDim.x + threadIdx.x;
    if (j < PRE_NMS) {
        int idx = g_top_idx[j];
        float4 a = *reinterpret_cast<const float4*>(amap + (size_t)idx*4);
        float4 d = *reinterpret_cast<const float4*>(out + NANCH + (size_t)idx*4);
        float cy = a.x + d.x * a.z;
        float cx = a.y + d.y * a.w;
        float hh = a.z * expf(d.z);
        float ww = a.w * expf(d.w);
        float y1 = cy - 0.5f*hh, x1 = cx - 0.5f*ww;
        float y2 = cy + 0.5f*hh, x2 = cx + 0.5f*ww;
        y1 = fmaxf(y1, 0.f); x1 = fmaxf(x1, 0.f);
        y2 = fminf(y2, IMG_H); x2 = fminf(x2, IMG_W);
        float bh = y2 - y1, bw = x2 - x1;
        bool valid = (bh >= 16.f) && (bw >= 16.f);
        g_by1[j] = y1; g_bx1[j] = x1; g_by2[j] = y2; g_bx2[j] = x2;
        g_nsc[j] = valid ? g_top_score[j] : NEGV;
    }
}

// ---------------- NMS: sorted-order pointer walk + in-smem parallel suppression ----------------
__global__ void nms_kernel(float* __restrict__ out) {
    extern __shared__ float sm[];
    float *sy1 = sm, *sx1 = sm+6000, *sy2 = sm+12000, *sx2 = sm+18000, *sar = sm+24000;
    unsigned char* sup = (unsigned char*)(sm + 30000);
    __shared__ int s_ptr;
    int t = threadIdx.x;

    for (int j = t; j < PRE_NMS; j += 1024) {
        float y1 = g_by1[j], x1 = g_bx1[j], y2 = g_by2[j], x2 = g_bx2[j];
        sy1[j] = y1; sx1[j] = x1; sy2[j] = y2; sx2[j] = x2;
        sar[j] = (y2 - y1) * (x2 - x1);
        sup[j] = (g_nsc[j] == NEGV) ? 1 : 0;
    }
    if (t == 0) s_ptr = 0;
    __syncthreads();

    for (int r = 0; r < POST_NMS; r++) {
        if (t < 32) {
            int p = s_ptr;
            while (p < PRE_NMS) {
                int idx = p + t;
                int a = (idx < PRE_NMS) ? (int)sup[idx] : 0;
                unsigned m = __ballot_sync(0xffffffffu, a == 0);
                if (m) { p += __ffs(m) - 1; break; }
                p += 32;
            }
            if (p > PRE_NMS) p = PRE_NMS;
            if (t == 0) s_ptr = p;
        }
        __syncthreads();

        int best = s_ptr;
        bool ok = best < PRE_NMS;
        if (ok) {
            float by1 = sy1[best], bx1 = sx1[best], by2 = sy2[best], bx2 = sx2[best], ba = sar[best];
            for (int j = best + 1 + t; j < PRE_NMS; j += 1024) {
                if (!sup[j]) {
                    float iy1 = fmaxf(sy1[j], by1), ix1 = fmaxf(sx1[j], bx1);
                    float iy2 = fminf(sy2[j], by2), ix2 = fminf(sx2[j], bx2);
                    float dy = iy2 - iy1, dx = ix2 - ix1;
                    if (dy > 0.f && dx > 0.f) {
                        float inter = dy * dx;
                        float iou = inter / (sar[j] + ba - inter + 1e-8f);
                        if (iou > 0.7f) sup[j] = 1;
                    }
                }
            }
            if (t == 0) {
                sup[best] = 1;
                reinterpret_cast<float4*>(out + NANCH + NANCH*4)[r] =
                    make_float4(by1, bx1, by2, bx2);
            }
        } else if (t == 0) {
            reinterpret_cast<float4*>(out + NANCH + NANCH*4)[r] =
                make_float4(0.f, 0.f, 0.f, 0.f);
        }
        __syncthreads();
    }
}

// ---------------- launch ----------------
extern "C" void kernel_launch(void* const* d_in, const int* in_sizes, int n_in,
                              void* d_out, int out_size) {
    const float* fm   = (const float*)d_in[1];
    const float* amap = (const float*)d_in[2];
    const float* W1   = (const float*)d_in[3];
    const float* b1   = (const float*)d_in[4];
    const float* Wc   = (const float*)d_in[5];
    const float* bc   = (const float*)d_in[6];
    const float* Wr   = (const float*)d_in[7];
    const float* br   = (const float*)d_in[8];
    float* out = (float*)d_out;

    cudaFuncSetAttribute(sort_kernel, cudaFuncAttributeMaxDynamicSharedMemorySize, 8192*8);
    cudaFuncSetAttribute(nms_kernel,  cudaFuncAttributeMaxDynamicSharedMemorySize, 30000*4 + 6000);
    cudaFuncSetAttribute(conv_mma_kernel, cudaFuncAttributeMaxDynamicSharedMemorySize, CONV_SMEM);

    // heads is the 4th launch -> it is the kernel ncu captures this round
    fused_pack_kernel<<<PACK_TOTAL, 256>>>(fm, W1, Wc, Wr);
    zero_kernel<<<513, 256>>>();
    conv_mma_kernel<<<dim3(10, 13, 8), 256, CONV_SMEM>>>(b1);
    heads_kernel<<<2000, 384>>>(bc, br, out);       // also builds hist1

    find_bin1_kernel<<<1, 1024>>>();
    hist2_kernel<<<563, 256>>>(out);
    find_thresh_kernel<<<1, 1024>>>();
    compact_kernel<<<563, 256>>>(out);
    eq_rank_kernel<<<32, 256>>>();
    sort_kernel<<<1, 1024, 8192*8>>>();
    decode_kernel<<<24, 256>>>(amap, out);
    nms_kernel<<<1, 1024, 30000*4 + 6000>>>(out);
}

// round 14
// speedup vs baseline: 1.0463x; 1.0463x over previous
#include <cuda_runtime.h>
#include <cuda_fp16.h>
#include <math.h>
#include <stdint.h>

#define HF 100
#define WF 160
#define CIN 512
#define CC 512
#define NA 9
#define NPIX (HF*WF)
#define NANCH (NPIX*NA)      // 144000
#define PRE_NMS 6000
#define POST_NMS 300
#define NEGV -1e9f
#define IMG_H 1600.0f
#define IMG_W 2560.0f

// ---------------- device scratch (no allocations allowed) ----------------
__device__ float  g_y[NPIX*CC];                // conv output (relu'd), 32.8 MB
__device__ __half g_fm_h[NPIX*CIN];            // fp16 hi of feature map
__device__ __half g_fm_l[NPIX*CIN];            // fp16 lo*2048
__device__ __half g_w_h[9*CC*CIN];             // [tap][co][cin] hi
__device__ __half g_w_l[9*CC*CIN];             // lo*2048
__device__ float  g_hw2[512*45];               // heads weights [k][o] (o minor)
__device__ unsigned int g_hist1[65536];
__device__ unsigned int g_hist2[65536];
__device__ unsigned int g_binB, g_rank_before, g_T, g_G, g_need_eq;
__device__ unsigned int g_cnt_gt, g_eq_cnt;
__device__ unsigned long long g_pairs[8192];
__device__ unsigned int g_eq_idx[NANCH];
__device__ int   g_top_idx[PRE_NMS];
__device__ float g_top_score[PRE_NMS];
__device__ float g_by1[PRE_NMS], g_bx1[PRE_NMS], g_by2[PRE_NMS], g_bx2[PRE_NMS];
__device__ float g_nsc[PRE_NMS];

// ================= helpers =================
static __device__ __forceinline__ uint32_t smem_u32(const void* p) {
    uint32_t a;
    asm("{ .reg .u64 t; cvta.to.shared.u64 t, %1; cvt.u32.u64 %0, t; }" : "=r"(a) : "l"(p));
    return a;
}
static __device__ __forceinline__ void cpa16(uint32_t dst, const void* src, uint32_t sz) {
    asm volatile("cp.async.cg.shared.global [%0], [%1], 16, %2;" :: "r"(dst), "l"(src), "r"(sz) : "memory");
}
static __device__ __forceinline__ void cpa16f(uint32_t dst, const void* src) {
    asm volatile("cp.async.cg.shared.global [%0], [%1], 16;" :: "r"(dst), "l"(src) : "memory");
}
#define CP_COMMIT() asm volatile("cp.async.commit_group;" ::: "memory")
#define CP_WAIT2()  asm volatile("cp.async.wait_group 2;" ::: "memory")

static __device__ __forceinline__ void ldsm4(uint32_t* r, uint32_t addr) {
    asm volatile("ldmatrix.sync.aligned.m8n8.x4.shared.b16 {%0,%1,%2,%3}, [%4];"
        : "=r"(r[0]), "=r"(r[1]), "=r"(r[2]), "=r"(r[3]) : "r"(addr));
}
static __device__ __forceinline__ void mma16(float* d, const uint32_t* a, uint32_t b0, uint32_t b1) {
    asm volatile(
        "mma.sync.aligned.m16n8k16.row.col.f32.f16.f16.f32 "
        "{%0,%1,%2,%3}, {%4,%5,%6,%7}, {%8,%9}, {%0,%1,%2,%3};"
        : "+f"(d[0]), "+f"(d[1]), "+f"(d[2]), "+f"(d[3])
        : "r"(a[0]), "r"(a[1]), "r"(a[2]), "r"(a[3]), "r"(b0), "r"(b1));
}

// ================= packing (fp16 hi + scaled lo) =================
__global__ void pack_fm_kernel(const float* __restrict__ fm) {
    int i = blockIdx.x*blockDim.x + threadIdx.x;
    if (i < NPIX*CIN) {
        float x = fm[i];
        __half h = __float2half_rn(x);
        float  r = x - __half2float(h);
        g_fm_h[i] = h;
        g_fm_l[i] = __float2half_rn(r * 2048.0f);
    }
}
__global__ void pack_w_kernel(const float* __restrict__ W1) {
    int i = blockIdx.x*blockDim.x + threadIdx.x;
    if (i < 9*CIN*CC) {
        int tap = i / (CIN*CC), rem = i - tap*(CIN*CC);
        int cin = rem >> 9, co = rem & 511;           // W1 is [tap][cin][co]
        float x = W1[i];
        __half h = __float2half_rn(x);
        float  r = x - __half2float(h);
        size_t dst = ((size_t)tap*CC + co)*CIN + cin; // [tap][co][cin]
        g_w_h[dst] = h;
        g_w_l[dst] = __float2half_rn(r * 2048.0f);
    }
}
__global__ void heads_pack_kernel(const float* __restrict__ Wc, const float* __restrict__ Wr) {
    int i = blockIdx.x*blockDim.x + threadIdx.x;
    if (i < 512*45) {
        int k = i / 45, o = i - k*45;
        g_hw2[i] = (o < 9) ? Wc[k*9 + o] : Wr[k*36 + (o-9)];
    }
}

// ================= conv 3x3 512->512 via mma.sync fp16 (3-term split) =================
// R6 tiling (8x16 px x 64 co, ROWB=48, K=16/iter), paired iterations (R10): 144 super-iters.
#define ROWB  48
#define SEG_A (180*ROWB)       // 8640 (one of hi/lo)
#define ABUF  (2*SEG_A)        // 17280
#define SEG_B (64*ROWB)        // 3072
#define BSTG  (2*SEG_B)        // 6144
#define BOFF  (2*ABUF)         // 34560
#define NBSTG 6
#define CONV_SMEM (BOFF + NBSTG*BSTG)   // 71424 B

__global__ __launch_bounds__(256, 2) void conv_mma_kernel(const float* __restrict__ b1) {
    extern __shared__ char smraw[];
    uint32_t sb = smem_u32(smraw);
    int t = threadIdx.x;
    int row0 = blockIdx.y * 8;
    int col0 = blockIdx.x * 16;
    int n0   = blockIdx.z * 64;
    int wid = t >> 5, lane = t & 31;
    int g = lane >> 2, tg = lane & 3;
    int wm = wid >> 1, wn = wid & 1;
    int r8 = lane & 7, sel = lane >> 3;

    uint32_t aOff[2];
    {
        int apix = r8 + ((sel & 1) ? 8 : 0);
        int akb  = (sel & 2) ? 16 : 0;
        #pragma unroll
        for (int mt = 0; mt < 2; mt++)
            aOff[mt] = (uint32_t)(((2*wm + mt)*18 + apix)*ROWB + akb);
    }
    uint32_t bOff[2];
    {
        int bco = r8 + ((sel & 2) ? 8 : 0);
        int bkb = (sel & 1) ? 16 : 0;
        #pragma unroll
        for (int q = 0; q < 2; q++)
            bOff[q] = (uint32_t)((wn*32 + q*16 + bco)*ROWB + bkb);
    }

    float accD[2][4][4], accE[2][4][4];
    #pragma unroll
    for (int mt = 0; mt < 2; mt++)
        #pragma unroll
        for (int nt = 0; nt < 4; nt++)
            #pragma unroll
            for (int v = 0; v < 4; v++) { accD[mt][nt][v] = 0.f; accE[mt][nt][v] = 0.f; }

    auto loadA = [&](int buf, int cc) {
        uint32_t Ab = sb + buf*ABUF;
        #pragma unroll 1
        for (int o = t; o < 720; o += 256) {
            int pix = o >> 2, part = o & 3;
            int seg = part >> 1, hh = part & 1;
            int hr = pix / 18, hc = pix - hr*18;
            int gr = row0 - 1 + hr, gc = col0 - 1 + hc;
            bool v = ((unsigned)gr < (unsigned)HF) && ((unsigned)gc < (unsigned)WF);
            const __half* base = seg ? g_fm_l : g_fm_h;
            const __half* src = v ? (base + (size_t)(gr*WF + gc)*CIN + cc*16 + hh*8) : base;
            cpa16(Ab + (uint32_t)(seg*SEG_A + pix*ROWB + hh*16), src, v ? 16u : 0u);
        }
    };
    auto loadB = [&](int buf, int tap, int cc) {
        uint32_t Bb = sb + BOFF + buf*BSTG;
        int co = t >> 2, part = t & 3;
        int seg = part >> 1, hh = part & 1;
        const __half* base = seg ? g_w_l : g_w_h;
        cpa16f(Bb + (uint32_t)(seg*SEG_B + co*ROWB + hh*16),
               base + ((size_t)tap*CC + n0 + co)*CIN + cc*16 + hh*8);
    };

    auto compute_iter = [&](int j) {
        int cc = j / 9, tap = j - cc*9;
        uint32_t tapAdd = (uint32_t)(((tap/3)*18 + (tap%3))*ROWB);
        uint32_t Ab = sb + (cc & 1)*ABUF + tapAdd;
        uint32_t Bb = sb + BOFF + (j % NBSTG)*BSTG;

        uint32_t a_h[2][4], a_l[2][4], b_h[2][4], b_l[2][4];
        #pragma unroll
        for (int mt = 0; mt < 2; mt++) {
            ldsm4(a_h[mt], Ab + aOff[mt]);
            ldsm4(a_l[mt], Ab + SEG_A + aOff[mt]);
        }
        #pragma unroll
        for (int q = 0; q < 2; q++) {
            ldsm4(b_h[q], Bb + bOff[q]);
            ldsm4(b_l[q], Bb + SEG_B + bOff[q]);
        }
        #pragma unroll
        for (int mt = 0; mt < 2; mt++)
            #pragma unroll
            for (int nt = 0; nt < 4; nt++) {
                int q = nt >> 1, h2 = (nt & 1)*2;
                mma16(accD[mt][nt], a_h[mt], b_h[q][h2], b_h[q][h2+1]);
                mma16(accE[mt][nt], a_l[mt], b_h[q][h2], b_h[q][h2+1]);
                mma16(accE[mt][nt], a_h[mt], b_l[q][h2], b_l[q][h2+1]);
            }
    };

    loadA(0, 0);
    loadB(0, 0, 0); CP_COMMIT();
    loadB(1, 1, 0); CP_COMMIT();
    loadB(2, 2, 0); CP_COMMIT();
    loadB(3, 3, 0); CP_COMMIT();

    for (int s = 0; s < 144; s++) {
        CP_WAIT2();
        __syncthreads();
        #pragma unroll
        for (int e = 0; e < 2; e++) {
            int j = 2*s + 4 + e;
            if (j < 288) {
                int ncc = j / 9, ntap = j - ncc*9;
                if (ntap == 0) loadA(ncc & 1, ncc);
                loadB(j % NBSTG, ntap, ncc);
            }
            CP_COMMIT();
        }
        compute_iter(2*s);
        compute_iter(2*s + 1);
    }

    const float INV2048 = 1.0f/2048.0f;
    #pragma unroll
    for (int mt = 0; mt < 2; mt++) {
        int gr = row0 + 2*wm + mt;
        if (gr < HF) {
            int pixA = gr*WF + col0 + g;
            int pixB = pixA + 8;
            #pragma unroll
            for (int nt = 0; nt < 4; nt++) {
                int col = n0 + wn*32 + nt*8 + 2*tg;
                float bb0 = b1[col], bb1 = b1[col + 1];
                float2 oA, oB;
                oA.x = fmaxf(accD[mt][nt][0] + accE[mt][nt][0]*INV2048 + bb0, 0.f);
                oA.y = fmaxf(accD[mt][nt][1] + accE[mt][nt][1]*INV2048 + bb1, 0.f);
                oB.x = fmaxf(accD[mt][nt][2] + accE[mt][nt][2]*INV2048 + bb0, 0.f);
                oB.y = fmaxf(accD[mt][nt][3] + accE[mt][nt][3]*INV2048 + bb1, 0.f);
                *reinterpret_cast<float2*>(g_y + (size_t)pixA*512 + col) = oA;
                *reinterpret_cast<float2*>(g_y + (size_t)pixB*512 + col) = oB;
            }
        }
    }
}

// ---------------- 1x1 heads v4: 32 px/block, 4 pixels per thread (ws LDS amortized) ----------------
// Per-(pixel,o) accumulation order identical to R12 -> bit-identical outputs.
__global__ __launch_bounds__(384) void heads_kernel(const float* __restrict__ bc,
                                                    const float* __restrict__ br,
                                                    float* __restrict__ out) {
    __shared__ float ys[32*128];      // 16 KB
    __shared__ float ws[128*45];      // 22.5 KB
    __shared__ float lg[32][9];

    int t  = threadIdx.x;
    int p0 = blockIdx.x * 32;
    int pp = t / 45, o = t - pp*45;   // pp in 0..7 handles pixels pp*4..pp*4+3

    float acc[4] = {0.f, 0.f, 0.f, 0.f};
    for (int c0 = 0; c0 < 512; c0 += 128) {
        __syncthreads();
        for (int idx = t; idx < 1024; idx += 384) {
            int pix = idx >> 5, v = idx & 31;
            *reinterpret_cast<float4*>(ys + pix*128 + v*4) =
                *reinterpret_cast<const float4*>(g_y + (size_t)(p0+pix)*512 + c0 + v*4);
        }
        {
            float4* ws4 = reinterpret_cast<float4*>(ws);
            const float4* gw4 = reinterpret_cast<const float4*>(g_hw2 + c0*45);
            for (int i = t; i < 1440; i += 384) ws4[i] = gw4[i];
        }
        __syncthreads();
        if (t < 360) {
            const float4* yv0 = reinterpret_cast<const float4*>(ys + (pp*4+0)*128);
            const float4* yv1 = reinterpret_cast<const float4*>(ys + (pp*4+1)*128);
            const float4* yv2 = reinterpret_cast<const float4*>(ys + (pp*4+2)*128);
            const float4* yv3 = reinterpret_cast<const float4*>(ys + (pp*4+3)*128);
            #pragma unroll 4
            for (int k4 = 0; k4 < 32; k4++) {
                float w0 = ws[(k4*4+0)*45+o];
                float w1 = ws[(k4*4+1)*45+o];
                float w2 = ws[(k4*4+2)*45+o];
                float w3 = ws[(k4*4+3)*45+o];
                float4 y0 = yv0[k4], y1 = yv1[k4], y2 = yv2[k4], y3 = yv3[k4];
                acc[0] = fmaf(y0.x, w0, acc[0]); acc[0] = fmaf(y0.y, w1, acc[0]);
                acc[0] = fmaf(y0.z, w2, acc[0]); acc[0] = fmaf(y0.w, w3, acc[0]);
                acc[1] = fmaf(y1.x, w0, acc[1]); acc[1] = fmaf(y1.y, w1, acc[1]);
                acc[1] = fmaf(y1.z, w2, acc[1]); acc[1] = fmaf(y1.w, w3, acc[1]);
                acc[2] = fmaf(y2.x, w0, acc[2]); acc[2] = fmaf(y2.y, w1, acc[2]);
                acc[2] = fmaf(y2.z, w2, acc[2]); acc[2] = fmaf(y2.w, w3, acc[2]);
                acc[3] = fmaf(y3.x, w0, acc[3]); acc[3] = fmaf(y3.y, w1, acc[3]);
                acc[3] = fmaf(y3.z, w2, acc[3]); acc[3] = fmaf(y3.w, w3, acc[3]);
            }
        }
    }

    if (t < 360) {
        #pragma unroll
        for (int px = 0; px < 4; px++) {
            int gp = p0 + pp*4 + px;
            if (o < 9) lg[pp*4+px][o] = acc[px] + bc[o];
            else       out[NANCH + (size_t)gp*36 + (o-9)] = acc[px] + br[o-9];
        }
    }
    __syncthreads();
    if (t < 360 && o < 9) {
        #pragma unroll
        for (int px = 0; px < 4; px++) {
            int lp = pp*4 + px;
            int gp = p0 + lp;
            float m = lg[lp][0];
            #pragma unroll
            for (int j = 1; j < 9; j++) m = fmaxf(m, lg[lp][j]);
            float sum = 0.f;
            #pragma unroll
            for (int j = 0; j < 9; j++) sum += expf(lg[lp][j]-m);
            float sc = expf(lg[lp][o]-m)/sum;
            out[(size_t)gp*9 + o] = sc;
            atomicAdd(&g_hist1[__float_as_uint(sc) >> 16], 1u);
        }
    }
}

// ---------------- exact top-k(6000) via 2-level radix ----------------
__global__ void zero_kernel() {
    int i = blockIdx.x*blockDim.x + threadIdx.x;
    if (i < 65536) g_hist1[i] = 0u;
    else if (i < 131072) g_hist2[i-65536] = 0u;
    else if (i == 131072) { g_cnt_gt = 0u; g_eq_cnt = 0u; }
}

__global__ void find_bin1_kernel() {
    __shared__ unsigned csum[1024];
    int t = threadIdx.x;
    unsigned s = 0;
    for (int b = 0; b < 64; b++) s += g_hist1[t*64+b];
    csum[t] = s;
    __syncthreads();
    if (t == 0) {
        unsigned cum = 0; int chunk = 0;
        for (int q = 1023; q >= 0; q--) {
            if (cum + csum[q] >= (unsigned)PRE_NMS) { chunk = q; break; }
            cum += csum[q];
        }
        unsigned B = 0;
        for (int b = chunk*64+63; b >= chunk*64; b--) {
            unsigned h = g_hist1[b];
            if (cum + h >= (unsigned)PRE_NMS) { B = (unsigned)b; break; }
            cum += h;
        }
        g_binB = B; g_rank_before = cum;
    }
}

__global__ void hist2_kernel(const float* __restrict__ out) {
    int i = blockIdx.x*blockDim.x + threadIdx.x;
    unsigned u = 0; bool p = false;
    if (i < NANCH) {
        u = __float_as_uint(out[i]);
        p = (u >> 16) == g_binB;
    }
    unsigned amask = __ballot_sync(0xffffffffu, p);
    if (p) {
        unsigned low = u & 0xFFFFu;
        unsigned m = __match_any_sync(amask, low);
        if ((int)(threadIdx.x & 31) == __ffs(m) - 1)
            atomicAdd(&g_hist2[low], (unsigned)__popc(m));
    }
}

__global__ void find_thresh_kernel() {
    __shared__ unsigned csum[1024];
    int t = threadIdx.x;
    unsigned s = 0;
    for (int b = 0; b < 64; b++) s += g_hist2[t*64+b];
    csum[t] = s;
    __syncthreads();
    if (t == 0) {
        unsigned cum = g_rank_before; int chunk = 0;
        for (int q = 1023; q >= 0; q--) {
            if (cum + csum[q] >= (unsigned)PRE_NMS) { chunk = q; break; }
            cum += csum[q];
        }
        unsigned L = 0;
        for (int b = chunk*64+63; b >= chunk*64; b--) {
            unsigned h = g_hist2[b];
            if (cum + h >= (unsigned)PRE_NMS) { L = (unsigned)b; break; }
            cum += h;
        }
        g_T = (g_binB << 16) | L;
        g_G = cum;
        g_need_eq = (unsigned)PRE_NMS - cum;
    }
}

__global__ void compact_kernel(const float* __restrict__ out) {
    int i = blockIdx.x*blockDim.x + threadIdx.x;
    if (i < NANCH) {
        unsigned u = __float_as_uint(out[i]);
        unsigned T = g_T;
        if (u > T) {
            unsigned pos = atomicAdd(&g_cnt_gt, 1u);
            g_pairs[pos] = (((unsigned long long)u) << 32) | (unsigned)(~(unsigned)i);
        } else if (u == T) {
            unsigned pos = atomicAdd(&g_eq_cnt, 1u);
            g_eq_idx[pos] = (unsigned)i;
        }
    }
}

__global__ void eq_rank_kernel() {
    unsigned E = g_eq_cnt, need = g_need_eq, G = g_G, T = g_T;
    for (unsigned e = blockIdx.x*blockDim.x + threadIdx.x; e < E; e += gridDim.x*blockDim.x) {
        unsigned idx = g_eq_idx[e];
        unsigned rank = 0;
        for (unsigned f = 0; f < E; f++) rank += (g_eq_idx[f] < idx) ? 1u : 0u;
        if (rank < need)
            g_pairs[G + rank] = (((unsigned long long)T) << 32) | (unsigned)(~idx);
    }
}

__global__ void sort_kernel() {
    extern __shared__ unsigned long long sk[];
    int t = threadIdx.x;
    for (int j = t; j < 8192; j += 1024) sk[j] = (j < PRE_NMS) ? g_pairs[j] : 0ULL;
    __syncthreads();
    for (int k = 2; k <= 8192; k <<= 1) {
        for (int j = k >> 1; j > 0; j >>= 1) {
            for (int idx = t; idx < 8192; idx += 1024) {
                int ixj = idx ^ j;
                if (ixj > idx) {
                    unsigned long long a = sk[idx], b = sk[ixj];
                    bool desc = (idx & k) == 0;
                    if (desc ? (a < b) : (a > b)) { sk[idx] = b; sk[ixj] = a; }
                }
            }
            __syncthreads();
        }
    }
    for (int j = t; j < PRE_NMS; j += 1024) {
        unsigned long long p = sk[j];
        unsigned u = (unsigned)(p >> 32);
        unsigned idx = ~((unsigned)p);
        g_top_idx[j] = (int)idx;
        g_top_score[j] = __uint_as_float(u);
    }
}

__global__ void decode_kernel(const float* __restrict__ amap, const float* __restrict__ out) {
    int j = blockIdx.x*blockDim.x + threadIdx.x;
    if (j < PRE_NMS) {
        int idx = g_top_idx[j];
        float4 a = *reinterpret_cast<const float4*>(amap + (size_t)idx*4);
        float4 d = *reinterpret_cast<const float4*>(out + NANCH + (size_t)idx*4);
        float cy = a.x + d.x * a.z;
        float cx = a.y + d.y * a.w;
        float hh = a.z * expf(d.z);
        float ww = a.w * expf(d.w);
        float y1 = cy - 0.5f*hh, x1 = cx - 0.5f*ww;
        float y2 = cy + 0.5f*hh, x2 = cx + 0.5f*ww;
        y1 = fmaxf(y1, 0.f); x1 = fmaxf(x1, 0.f);
        y2 = fminf(y2, IMG_H); x2 = fminf(x2, IMG_W);
        float bh = y2 - y1, bw = x2 - x1;
        bool valid = (bh >= 16.f) && (bw >= 16.f);
        g_by1[j] = y1; g_bx1[j] = x1; g_by2[j] = y2; g_bx2[j] = x2;
        g_nsc[j] = valid ? g_top_score[j] : NEGV;
    }
}

// ---------------- NMS: sorted-order pointer walk + in-smem parallel suppression ----------------
__global__ void nms_kernel(float* __restrict__ out) {
    extern __shared__ float sm[];
    float *sy1 = sm, *sx1 = sm+6000, *sy2 = sm+12000, *sx2 = sm+18000, *sar = sm+24000;
    unsigned char* sup = (unsigned char*)(sm + 30000);
    __shared__ int s_ptr;
    int t = threadIdx.x;

    for (int j = t; j < PRE_NMS; j += 1024) {
        float y1 = g_by1[j], x1 = g_bx1[j], y2 = g_by2[j], x2 = g_bx2[j];
        sy1[j] = y1; sx1[j] = x1; sy2[j] = y2; sx2[j] = x2;
        sar[j] = (y2 - y1) * (x2 - x1);
        sup[j] = (g_nsc[j] == NEGV) ? 1 : 0;
    }
    if (t == 0) s_ptr = 0;
    __syncthreads();

    for (int r = 0; r < POST_NMS; r++) {
        if (t < 32) {
            int p = s_ptr;
            while (p < PRE_NMS) {
                int idx = p + t;
                int a = (idx < PRE_NMS) ? (int)sup[idx] : 0;
                unsigned m = __ballot_sync(0xffffffffu, a == 0);
                if (m) { p += __ffs(m) - 1; break; }
                p += 32;
            }
            if (p > PRE_NMS) p = PRE_NMS;
            if (t == 0) s_ptr = p;
        }
        __syncthreads();

        int best = s_ptr;
        bool ok = best < PRE_NMS;
        if (ok) {
            float by1 = sy1[best], bx1 = sx1[best], by2 = sy2[best], bx2 = sx2[best], ba = sar[best];
            for (int j = best + 1 + t; j < PRE_NMS; j += 1024) {
                if (!sup[j]) {
                    float iy1 = fmaxf(sy1[j], by1), ix1 = fmaxf(sx1[j], bx1);
                    float iy2 = fminf(sy2[j], by2), ix2 = fminf(sx2[j], bx2);
                    float dy = iy2 - iy1, dx = ix2 - ix1;
                    if (dy > 0.f && dx > 0.f) {
                        float inter = dy * dx;
                        float iou = inter / (sar[j] + ba - inter + 1e-8f);
                        if (iou > 0.7f) sup[j] = 1;
                    }
                }
            }
            if (t == 0) {
                sup[best] = 1;
                reinterpret_cast<float4*>(out + NANCH + NANCH*4)[r] =
                    make_float4(by1, bx1, by2, bx2);
            }
        } else if (t == 0) {
            reinterpret_cast<float4*>(out + NANCH + NANCH*4)[r] =
                make_float4(0.f, 0.f, 0.f, 0.f);
        }
        __syncthreads();
    }
}

// ---------------- launch ----------------
extern "C" void kernel_launch(void* const* d_in, const int* in_sizes, int n_in,
                              void* d_out, int out_size) {
    const float* fm   = (const float*)d_in[1];
    const float* amap = (const float*)d_in[2];
    const float* W1   = (const float*)d_in[3];
    const float* b1   = (const float*)d_in[4];
    const float* Wc   = (const float*)d_in[5];
    const float* bc   = (const float*)d_in[6];
    const float* Wr   = (const float*)d_in[7];
    const float* br   = (const float*)d_in[8];
    float* out = (float*)d_out;

    cudaFuncSetAttribute(sort_kernel, cudaFuncAttributeMaxDynamicSharedMemorySize, 8192*8);
    cudaFuncSetAttribute(nms_kernel,  cudaFuncAttributeMaxDynamicSharedMemorySize, 30000*4 + 6000);
    cudaFuncSetAttribute(conv_mma_kernel, cudaFuncAttributeMaxDynamicSharedMemorySize, CONV_SMEM);

    // conv is the 4th launch -> it is the kernel ncu captures
    pack_fm_kernel<<<32000, 256>>>(fm);
    pack_w_kernel<<<9216, 256>>>(W1);
    heads_pack_kernel<<<90, 256>>>(Wc, Wr);
    conv_mma_kernel<<<dim3(10, 13, 8), 256, CONV_SMEM>>>(b1);
    zero_kernel<<<513, 256>>>();

    heads_kernel<<<500, 384>>>(bc, br, out);        // also builds hist1
    find_bin1_kernel<<<1, 1024>>>();
    hist2_kernel<<<563, 256>>>(out);
    find_thresh_kernel<<<1, 1024>>>();
    compact_kernel<<<563, 256>>>(out);
    eq_rank_kernel<<<32, 256>>>();
    sort_kernel<<<1, 1024, 8192*8>>>();
    decode_kernel<<<24, 256>>>(amap, out);
    nms_kernel<<<1, 1024, 30000*4 + 6000>>>(out);
}

// round 15
// speedup vs baseline: 1.0759x; 1.0282x over previous
#include <cuda_runtime.h>
#include <cuda_fp16.h>
#include <math.h>
#include <stdint.h>

#define HF 100
#define WF 160
#define CIN 512
#define CC 512
#define NA 9
#define NPIX (HF*WF)
#define NANCH (NPIX*NA)      // 144000
#define PRE_NMS 6000
#define POST_NMS 300
#define NEGV -1e9f
#define IMG_H 1600.0f
#define IMG_W 2560.0f

// ---------------- device scratch (no allocations allowed) ----------------
__device__ float  g_y[NPIX*CC];                // conv output (relu'd), 32.8 MB
__device__ __half g_fm_h[NPIX*CIN];            // fp16 hi of feature map
__device__ __half g_fm_l[NPIX*CIN];            // fp16 lo*2048
__device__ __half g_w_h[9*CC*CIN];             // [tap][co][cin] hi
__device__ __half g_w_l[9*CC*CIN];             // lo*2048
__device__ float  g_hw2[512*45];               // heads weights [k][o] (o minor)
__device__ unsigned int g_hist1[65536];
__device__ unsigned int g_hist2[65536];
__device__ unsigned int g_binB, g_rank_before, g_T, g_G, g_need_eq;
__device__ unsigned int g_cnt_gt, g_eq_cnt;
__device__ unsigned long long g_pairs[8192];
__device__ unsigned int g_eq_idx[NANCH];
__device__ int   g_top_idx[PRE_NMS];
__device__ float g_top_score[PRE_NMS];
__device__ float g_by1[PRE_NMS], g_bx1[PRE_NMS], g_by2[PRE_NMS], g_bx2[PRE_NMS];
__device__ float g_nsc[PRE_NMS];

// ================= helpers =================
static __device__ __forceinline__ uint32_t smem_u32(const void* p) {
    uint32_t a;
    asm("{ .reg .u64 t; cvta.to.shared.u64 t, %1; cvt.u32.u64 %0, t; }" : "=r"(a) : "l"(p));
    return a;
}
static __device__ __forceinline__ void cpa16(uint32_t dst, const void* src, uint32_t sz) {
    asm volatile("cp.async.cg.shared.global [%0], [%1], 16, %2;" :: "r"(dst), "l"(src), "r"(sz) : "memory");
}
static __device__ __forceinline__ void cpa16f(uint32_t dst, const void* src) {
    asm volatile("cp.async.cg.shared.global [%0], [%1], 16;" :: "r"(dst), "l"(src) : "memory");
}
#define CP_COMMIT() asm volatile("cp.async.commit_group;" ::: "memory")
#define CP_WAIT2()  asm volatile("cp.async.wait_group 2;" ::: "memory")

static __device__ __forceinline__ void ldsm4(uint32_t* r, uint32_t addr) {
    asm volatile("ldmatrix.sync.aligned.m8n8.x4.shared.b16 {%0,%1,%2,%3}, [%4];"
        : "=r"(r[0]), "=r"(r[1]), "=r"(r[2]), "=r"(r[3]) : "r"(addr));
}
static __device__ __forceinline__ void mma16(float* d, const uint32_t* a, uint32_t b0, uint32_t b1) {
    asm volatile(
        "mma.sync.aligned.m16n8k16.row.col.f32.f16.f16.f32 "
        "{%0,%1,%2,%3}, {%4,%5,%6,%7}, {%8,%9}, {%0,%1,%2,%3};"
        : "+f"(d[0]), "+f"(d[1]), "+f"(d[2]), "+f"(d[3])
        : "r"(a[0]), "r"(a[1]), "r"(a[2]), "r"(a[3]), "r"(b0), "r"(b1));
}

// ================= packing (fp16 hi + scaled lo) =================
__global__ void pack_fm_kernel(const float* __restrict__ fm) {
    int i = blockIdx.x*blockDim.x + threadIdx.x;
    if (i < NPIX*CIN) {
        float x = fm[i];
        __half h = __float2half_rn(x);
        float  r = x - __half2float(h);
        g_fm_h[i] = h;
        g_fm_l[i] = __float2half_rn(r * 2048.0f);
    }
}
// transposing pack for W1: [tap][cin][co] -> [tap][co][cin]; both sides coalesced.
// Values bit-identical to the scalar version (same per-element conversion).
__global__ void pack_w_kernel(const float* __restrict__ W1) {
    __shared__ __half th[32][33];
    __shared__ __half tl[32][33];
    int tap = blockIdx.z;
    int cin0 = blockIdx.y*32, co0 = blockIdx.x*32;
    int tx = threadIdx.x, ty = threadIdx.y;   // 32 x 8
    #pragma unroll
    for (int r = 0; r < 32; r += 8) {
        float x = W1[((size_t)tap*512 + cin0 + ty + r)*512 + co0 + tx];
        __half h = __float2half_rn(x);
        float  rr = x - __half2float(h);
        th[ty + r][tx] = h;
        tl[ty + r][tx] = __float2half_rn(rr * 2048.0f);
    }
    __syncthreads();
    #pragma unroll
    for (int r = 0; r < 32; r += 8) {
        size_t dst = ((size_t)tap*512 + co0 + ty + r)*512 + cin0 + tx;
        g_w_h[dst] = th[tx][ty + r];
        g_w_l[dst] = tl[tx][ty + r];
    }
}
__global__ void heads_pack_kernel(const float* __restrict__ Wc, const float* __restrict__ Wr) {
    int i = blockIdx.x*blockDim.x + threadIdx.x;
    if (i < 512*45) {
        int k = i / 45, o = i - k*45;
        g_hw2[i] = (o < 9) ? Wc[k*9 + o] : Wr[k*36 + (o-9)];
    }
}

// ================= conv 3x3 512->512 via mma.sync fp16 (3-term split) =================
// R6 tiling (8x16 px x 64 co, ROWB=48, K=16/iter), paired iterations (R10): 144 super-iters.
#define ROWB  48
#define SEG_A (180*ROWB)       // 8640 (one of hi/lo)
#define ABUF  (2*SEG_A)        // 17280
#define SEG_B (64*ROWB)        // 3072
#define BSTG  (2*SEG_B)        // 6144
#define BOFF  (2*ABUF)         // 34560
#define NBSTG 6
#define CONV_SMEM (BOFF + NBSTG*BSTG)   // 71424 B

__global__ __launch_bounds__(256, 2) void conv_mma_kernel(const float* __restrict__ b1) {
    extern __shared__ char smraw[];
    uint32_t sb = smem_u32(smraw);
    int t = threadIdx.x;
    int row0 = blockIdx.y * 8;
    int col0 = blockIdx.x * 16;
    int n0   = blockIdx.z * 64;
    int wid = t >> 5, lane = t & 31;
    int g = lane >> 2, tg = lane & 3;
    int wm = wid >> 1, wn = wid & 1;
    int r8 = lane & 7, sel = lane >> 3;

    uint32_t aOff[2];
    {
        int apix = r8 + ((sel & 1) ? 8 : 0);
        int akb  = (sel & 2) ? 16 : 0;
        #pragma unroll
        for (int mt = 0; mt < 2; mt++)
            aOff[mt] = (uint32_t)(((2*wm + mt)*18 + apix)*ROWB + akb);
    }
    uint32_t bOff[2];
    {
        int bco = r8 + ((sel & 2) ? 8 : 0);
        int bkb = (sel & 1) ? 16 : 0;
        #pragma unroll
        for (int q = 0; q < 2; q++)
            bOff[q] = (uint32_t)((wn*32 + q*16 + bco)*ROWB + bkb);
    }

    float accD[2][4][4], accE[2][4][4];
    #pragma unroll
    for (int mt = 0; mt < 2; mt++)
        #pragma unroll
        for (int nt = 0; nt < 4; nt++)
            #pragma unroll
            for (int v = 0; v < 4; v++) { accD[mt][nt][v] = 0.f; accE[mt][nt][v] = 0.f; }

    auto loadA = [&](int buf, int cc) {
        uint32_t Ab = sb + buf*ABUF;
        #pragma unroll 1
        for (int o = t; o < 720; o += 256) {
            int pix = o >> 2, part = o & 3;
            int seg = part >> 1, hh = part & 1;
            int hr = pix / 18, hc = pix - hr*18;
            int gr = row0 - 1 + hr, gc = col0 - 1 + hc;
            bool v = ((unsigned)gr < (unsigned)HF) && ((unsigned)gc < (unsigned)WF);
            const __half* base = seg ? g_fm_l : g_fm_h;
            const __half* src = v ? (base + (size_t)(gr*WF + gc)*CIN + cc*16 + hh*8) : base;
            cpa16(Ab + (uint32_t)(seg*SEG_A + pix*ROWB + hh*16), src, v ? 16u : 0u);
        }
    };
    auto loadB = [&](int buf, int tap, int cc) {
        uint32_t Bb = sb + BOFF + buf*BSTG;
        int co = t >> 2, part = t & 3;
        int seg = part >> 1, hh = part & 1;
        const __half* base = seg ? g_w_l : g_w_h;
        cpa16f(Bb + (uint32_t)(seg*SEG_B + co*ROWB + hh*16),
               base + ((size_t)tap*CC + n0 + co)*CIN + cc*16 + hh*8);
    };

    auto compute_iter = [&](int j) {
        int cc = j / 9, tap = j - cc*9;
        uint32_t tapAdd = (uint32_t)(((tap/3)*18 + (tap%3))*ROWB);
        uint32_t Ab = sb + (cc & 1)*ABUF + tapAdd;
        uint32_t Bb = sb + BOFF + (j % NBSTG)*BSTG;

        uint32_t a_h[2][4], a_l[2][4], b_h[2][4], b_l[2][4];
        #pragma unroll
        for (int mt = 0; mt < 2; mt++) {
            ldsm4(a_h[mt], Ab + aOff[mt]);
            ldsm4(a_l[mt], Ab + SEG_A + aOff[mt]);
        }
        #pragma unroll
        for (int q = 0; q < 2; q++) {
            ldsm4(b_h[q], Bb + bOff[q]);
            ldsm4(b_l[q], Bb + SEG_B + bOff[q]);
        }
        #pragma unroll
        for (int mt = 0; mt < 2; mt++)
            #pragma unroll
            for (int nt = 0; nt < 4; nt++) {
                int q = nt >> 1, h2 = (nt & 1)*2;
                mma16(accD[mt][nt], a_h[mt], b_h[q][h2], b_h[q][h2+1]);
                mma16(accE[mt][nt], a_l[mt], b_h[q][h2], b_h[q][h2+1]);
                mma16(accE[mt][nt], a_h[mt], b_l[q][h2], b_l[q][h2+1]);
            }
    };

    loadA(0, 0);
    loadB(0, 0, 0); CP_COMMIT();
    loadB(1, 1, 0); CP_COMMIT();
    loadB(2, 2, 0); CP_COMMIT();
    loadB(3, 3, 0); CP_COMMIT();

    for (int s = 0; s < 144; s++) {
        CP_WAIT2();
        __syncthreads();
        #pragma unroll
        for (int e = 0; e < 2; e++) {
            int j = 2*s + 4 + e;
            if (j < 288) {
                int ncc = j / 9, ntap = j - ncc*9;
                if (ntap == 0) loadA(ncc & 1, ncc);
                loadB(j % NBSTG, ntap, ncc);
            }
            CP_COMMIT();
        }
        compute_iter(2*s);
        compute_iter(2*s + 1);
    }

    const float INV2048 = 1.0f/2048.0f;
    #pragma unroll
    for (int mt = 0; mt < 2; mt++) {
        int gr = row0 + 2*wm + mt;
        if (gr < HF) {
            int pixA = gr*WF + col0 + g;
            int pixB = pixA + 8;
            #pragma unroll
            for (int nt = 0; nt < 4; nt++) {
                int col = n0 + wn*32 + nt*8 + 2*tg;
                float bb0 = b1[col], bb1 = b1[col + 1];
                float2 oA, oB;
                oA.x = fmaxf(accD[mt][nt][0] + accE[mt][nt][0]*INV2048 + bb0, 0.f);
                oA.y = fmaxf(accD[mt][nt][1] + accE[mt][nt][1]*INV2048 + bb1, 0.f);
                oB.x = fmaxf(accD[mt][nt][2] + accE[mt][nt][2]*INV2048 + bb0, 0.f);
                oB.y = fmaxf(accD[mt][nt][3] + accE[mt][nt][3]*INV2048 + bb1, 0.f);
                *reinterpret_cast<float2*>(g_y + (size_t)pixA*512 + col) = oA;
                *reinterpret_cast<float2*>(g_y + (size_t)pixB*512 + col) = oB;
            }
        }
    }
}

// ---------------- 1x1 heads v4: 32 px/block, 4 pixels per thread (ws LDS amortized) ----------------
__global__ __launch_bounds__(384) void heads_kernel(const float* __restrict__ bc,
                                                    const float* __restrict__ br,
                                                    float* __restrict__ out) {
    __shared__ float ys[32*128];      // 16 KB
    __shared__ float ws[128*45];      // 22.5 KB
    __shared__ float lg[32][9];

    int t  = threadIdx.x;
    int p0 = blockIdx.x * 32;
    int pp = t / 45, o = t - pp*45;

    float acc[4] = {0.f, 0.f, 0.f, 0.f};
    for (int c0 = 0; c0 < 512; c0 += 128) {
        __syncthreads();
        for (int idx = t; idx < 1024; idx += 384) {
            int pix = idx >> 5, v = idx & 31;
            *reinterpret_cast<float4*>(ys + pix*128 + v*4) =
                *reinterpret_cast<const float4*>(g_y + (size_t)(p0+pix)*512 + c0 + v*4);
        }
        {
            float4* ws4 = reinterpret_cast<float4*>(ws);
            const float4* gw4 = reinterpret_cast<const float4*>(g_hw2 + c0*45);
            for (int i = t; i < 1440; i += 384) ws4[i] = gw4[i];
        }
        __syncthreads();
        if (t < 360) {
            const float4* yv0 = reinterpret_cast<const float4*>(ys + (pp*4+0)*128);
            const float4* yv1 = reinterpret_cast<const float4*>(ys + (pp*4+1)*128);
            const float4* yv2 = reinterpret_cast<const float4*>(ys + (pp*4+2)*128);
            const float4* yv3 = reinterpret_cast<const float4*>(ys + (pp*4+3)*128);
            #pragma unroll 4
            for (int k4 = 0; k4 < 32; k4++) {
                float w0 = ws[(k4*4+0)*45+o];
                float w1 = ws[(k4*4+1)*45+o];
                float w2 = ws[(k4*4+2)*45+o];
                float w3 = ws[(k4*4+3)*45+o];
                float4 y0 = yv0[k4], y1 = yv1[k4], y2 = yv2[k4], y3 = yv3[k4];
                acc[0] = fmaf(y0.x, w0, acc[0]); acc[0] = fmaf(y0.y, w1, acc[0]);
                acc[0] = fmaf(y0.z, w2, acc[0]); acc[0] = fmaf(y0.w, w3, acc[0]);
                acc[1] = fmaf(y1.x, w0, acc[1]); acc[1] = fmaf(y1.y, w1, acc[1]);
                acc[1] = fmaf(y1.z, w2, acc[1]); acc[1] = fmaf(y1.w, w3, acc[1]);
                acc[2] = fmaf(y2.x, w0, acc[2]); acc[2] = fmaf(y2.y, w1, acc[2]);
                acc[2] = fmaf(y2.z, w2, acc[2]); acc[2] = fmaf(y2.w, w3, acc[2]);
                acc[3] = fmaf(y3.x, w0, acc[3]); acc[3] = fmaf(y3.y, w1, acc[3]);
                acc[3] = fmaf(y3.z, w2, acc[3]); acc[3] = fmaf(y3.w, w3, acc[3]);
            }
        }
    }

    if (t < 360) {
        #pragma unroll
        for (int px = 0; px < 4; px++) {
            int gp = p0 + pp*4 + px;
            if (o < 9) lg[pp*4+px][o] = acc[px] + bc[o];
            else       out[NANCH + (size_t)gp*36 + (o-9)] = acc[px] + br[o-9];
        }
    }
    __syncthreads();
    if (t < 360 && o < 9) {
        #pragma unroll
        for (int px = 0; px < 4; px++) {
            int lp = pp*4 + px;
            int gp = p0 + lp;
            float m = lg[lp][0];
            #pragma unroll
            for (int j = 1; j < 9; j++) m = fmaxf(m, lg[lp][j]);
            float sum = 0.f;
            #pragma unroll
            for (int j = 0; j < 9; j++) sum += expf(lg[lp][j]-m);
            float sc = expf(lg[lp][o]-m)/sum;
            out[(size_t)gp*9 + o] = sc;
            atomicAdd(&g_hist1[__float_as_uint(sc) >> 16], 1u);
        }
    }
}

// ---------------- exact top-k(6000) via 2-level radix ----------------
__global__ void zero_kernel() {
    int i = blockIdx.x*blockDim.x + threadIdx.x;
    if (i < 65536) g_hist1[i] = 0u;
    else if (i < 131072) g_hist2[i-65536] = 0u;
    else if (i == 131072) { g_cnt_gt = 0u; g_eq_cnt = 0u; }
}

__global__ void find_bin1_kernel() {
    __shared__ unsigned csum[1024];
    int t = threadIdx.x;
    unsigned s = 0;
    for (int b = 0; b < 64; b++) s += g_hist1[t*64+b];
    csum[t] = s;
    __syncthreads();
    if (t == 0) {
        unsigned cum = 0; int chunk = 0;
        for (int q = 1023; q >= 0; q--) {
            if (cum + csum[q] >= (unsigned)PRE_NMS) { chunk = q; break; }
            cum += csum[q];
        }
        unsigned B = 0;
        for (int b = chunk*64+63; b >= chunk*64; b--) {
            unsigned h = g_hist1[b];
            if (cum + h >= (unsigned)PRE_NMS) { B = (unsigned)b; break; }
            cum += h;
        }
        g_binB = B; g_rank_before = cum;
    }
}

__global__ void hist2_kernel(const float* __restrict__ out) {
    int i = blockIdx.x*blockDim.x + threadIdx.x;
    unsigned u = 0; bool p = false;
    if (i < NANCH) {
        u = __float_as_uint(out[i]);
        p = (u >> 16) == g_binB;
    }
    unsigned amask = __ballot_sync(0xffffffffu, p);
    if (p) {
        unsigned low = u & 0xFFFFu;
        unsigned m = __match_any_sync(amask, low);
        if ((int)(threadIdx.x & 31) == __ffs(m) - 1)
            atomicAdd(&g_hist2[low], (unsigned)__popc(m));
    }
}

__global__ void find_thresh_kernel() {
    __shared__ unsigned csum[1024];
    int t = threadIdx.x;
    unsigned s = 0;
    for (int b = 0; b < 64; b++) s += g_hist2[t*64+b];
    csum[t] = s;
    __syncthreads();
    if (t == 0) {
        unsigned cum = g_rank_before; int chunk = 0;
        for (int q = 1023; q >= 0; q--) {
            if (cum + csum[q] >= (unsigned)PRE_NMS) { chunk = q; break; }
            cum += csum[q];
        }
        unsigned L = 0;
        for (int b = chunk*64+63; b >= chunk*64; b--) {
            unsigned h = g_hist2[b];
            if (cum + h >= (unsigned)PRE_NMS) { L = (unsigned)b; break; }
            cum += h;
        }
        g_T = (g_binB << 16) | L;
        g_G = cum;
        g_need_eq = (unsigned)PRE_NMS - cum;
    }
}

__global__ void compact_kernel(const float* __restrict__ out) {
    int i = blockIdx.x*blockDim.x + threadIdx.x;
    if (i < NANCH) {
        unsigned u = __float_as_uint(out[i]);
        unsigned T = g_T;
        if (u > T) {
            unsigned pos = atomicAdd(&g_cnt_gt, 1u);
            g_pairs[pos] = (((unsigned long long)u) << 32) | (unsigned)(~(unsigned)i);
        } else if (u == T) {
            unsigned pos = atomicAdd(&g_eq_cnt, 1u);
            g_eq_idx[pos] = (unsigned)i;
        }
    }
}

__global__ void eq_rank_kernel() {
    unsigned E = g_eq_cnt, need = g_need_eq, G = g_G, T = g_T;
    for (unsigned e = blockIdx.x*blockDim.x + threadIdx.x; e < E; e += gridDim.x*blockDim.x) {
        unsigned idx = g_eq_idx[e];
        unsigned rank = 0;
        for (unsigned f = 0; f < E; f++) rank += (g_eq_idx[f] < idx) ? 1u : 0u;
        if (rank < need)
            g_pairs[G + rank] = (((unsigned long long)T) << 32) | (unsigned)(~idx);
    }
}

__global__ void sort_kernel() {
    extern __shared__ unsigned long long sk[];
    int t = threadIdx.x;
    for (int j = t; j < 8192; j += 1024) sk[j] = (j < PRE_NMS) ? g_pairs[j] : 0ULL;
    __syncthreads();
    for (int k = 2; k <= 8192; k <<= 1) {
        for (int j = k >> 1; j > 0; j >>= 1) {
            for (int idx = t; idx < 8192; idx += 1024) {
                int ixj = idx ^ j;
                if (ixj > idx) {
                    unsigned long long a = sk[idx], b = sk[ixj];
                    bool desc = (idx & k) == 0;
                    if (desc ? (a < b) : (a > b)) { sk[idx] = b; sk[ixj] = a; }
                }
            }
            __syncthreads();
        }
    }
    for (int j = t; j < PRE_NMS; j += 1024) {
        unsigned long long p = sk[j];
        unsigned u = (unsigned)(p >> 32);
        unsigned idx = ~((unsigned)p);
        g_top_idx[j] = (int)idx;
        g_top_score[j] = __uint_as_float(u);
    }
}

__global__ void decode_kernel(const float* __restrict__ amap, const float* __restrict__ out) {
    int j = blockIdx.x*blockDim.x + threadIdx.x;
    if (j < PRE_NMS) {
        int idx = g_top_idx[j];
        float4 a = *reinterpret_cast<const float4*>(amap + (size_t)idx*4);
        float4 d = *reinterpret_cast<const float4*>(out + NANCH + (size_t)idx*4);
        float cy = a.x + d.x * a.z;
        float cx = a.y + d.y * a.w;
        float hh = a.z * expf(d.z);
        float ww = a.w * expf(d.w);
        float y1 = cy - 0.5f*hh, x1 = cx - 0.5f*ww;
        float y2 = cy + 0.5f*hh, x2 = cx + 0.5f*ww;
        y1 = fmaxf(y1, 0.f); x1 = fmaxf(x1, 0.f);
        y2 = fminf(y2, IMG_H); x2 = fminf(x2, IMG_W);
        float bh = y2 - y1, bw = x2 - x1;
        bool valid = (bh >= 16.f) && (bw >= 16.f);
        g_by1[j] = y1; g_bx1[j] = x1; g_by2[j] = y2; g_bx2[j] = x2;
        g_nsc[j] = valid ? g_top_score[j] : NEGV;
    }
}

// ---------------- NMS: sorted-order pointer walk + in-smem parallel suppression ----------------
__global__ void nms_kernel(float* __restrict__ out) {
    extern __shared__ float sm[];
    float *sy1 = sm, *sx1 = sm+6000, *sy2 = sm+12000, *sx2 = sm+18000, *sar = sm+24000;
    unsigned char* sup = (unsigned char*)(sm + 30000);
    __shared__ int s_ptr;
    int t = threadIdx.x;

    for (int j = t; j < PRE_NMS; j += 1024) {
        float y1 = g_by1[j], x1 = g_bx1[j], y2 = g_by2[j], x2 = g_bx2[j];
        sy1[j] = y1; sx1[j] = x1; sy2[j] = y2; sx2[j] = x2;
        sar[j] = (y2 - y1) * (x2 - x1);
        sup[j] = (g_nsc[j] == NEGV) ? 1 : 0;
    }
    if (t == 0) s_ptr = 0;
    __syncthreads();

    for (int r = 0; r < POST_NMS; r++) {
        if (t < 32) {
            int p = s_ptr;
            while (p < PRE_NMS) {
                int idx = p + t;
                int a = (idx < PRE_NMS) ? (int)sup[idx] : 0;
                unsigned m = __ballot_sync(0xffffffffu, a == 0);
                if (m) { p += __ffs(m) - 1; break; }
                p += 32;
            }
            if (p > PRE_NMS) p = PRE_NMS;
            if (t == 0) s_ptr = p;
        }
        __syncthreads();

        int best = s_ptr;
        bool ok = best < PRE_NMS;
        if (ok) {
            float by1 = sy1[best], bx1 = sx1[best], by2 = sy2[best], bx2 = sx2[best], ba = sar[best];
            for (int j = best + 1 + t; j < PRE_NMS; j += 1024) {
                if (!sup[j]) {
                    float iy1 = fmaxf(sy1[j], by1), ix1 = fmaxf(sx1[j], bx1);
                    float iy2 = fminf(sy2[j], by2), ix2 = fminf(sx2[j], bx2);
                    float dy = iy2 - iy1, dx = ix2 - ix1;
                    if (dy > 0.f && dx > 0.f) {
                        float inter = dy * dx;
                        float iou = inter / (sar[j] + ba - inter + 1e-8f);
                        if (iou > 0.7f) sup[j] = 1;
                    }
                }
            }
            if (t == 0) {
                sup[best] = 1;
                reinterpret_cast<float4*>(out + NANCH + NANCH*4)[r] =
                    make_float4(by1, bx1, by2, bx2);
            }
        } else if (t == 0) {
            reinterpret_cast<float4*>(out + NANCH + NANCH*4)[r] =
                make_float4(0.f, 0.f, 0.f, 0.f);
        }
        __syncthreads();
    }
}

// ---------------- launch ----------------
extern "C" void kernel_launch(void* const* d_in, const int* in_sizes, int n_in,
                              void* d_out, int out_size) {
    const float* fm   = (const float*)d_in[1];
    const float* amap = (const float*)d_in[2];
    const float* W1   = (const float*)d_in[3];
    const float* b1   = (const float*)d_in[4];
    const float* Wc   = (const float*)d_in[5];
    const float* bc   = (const float*)d_in[6];
    const float* Wr   = (const float*)d_in[7];
    const float* br   = (const float*)d_in[8];
    float* out = (float*)d_out;

    cudaFuncSetAttribute(sort_kernel, cudaFuncAttributeMaxDynamicSharedMemorySize, 8192*8);
    cudaFuncSetAttribute(nms_kernel,  cudaFuncAttributeMaxDynamicSharedMemorySize, 30000*4 + 6000);
    cudaFuncSetAttribute(conv_mma_kernel, cudaFuncAttributeMaxDynamicSharedMemorySize, CONV_SMEM);

    // conv is the 4th launch -> it is the kernel ncu captures
    pack_fm_kernel<<<32000, 256>>>(fm);
    pack_w_kernel<<<dim3(16, 16, 9), dim3(32, 8)>>>(W1);
    heads_pack_kernel<<<90, 256>>>(Wc, Wr);
    conv_mma_kernel<<<dim3(10, 13, 8), 256, CONV_SMEM>>>(b1);
    zero_kernel<<<513, 256>>>();

    heads_kernel<<<500, 384>>>(bc, br, out);        // also builds hist1
    find_bin1_kernel<<<1, 1024>>>();
    hist2_kernel<<<563, 256>>>(out);
    find_thresh_kernel<<<1, 1024>>>();
    compact_kernel<<<563, 256>>>(out);
    eq_rank_kernel<<<32, 256>>>();
    sort_kernel<<<1, 1024, 8192*8>>>();
    decode_kernel<<<24, 256>>>(amap, out);
    nms_kernel<<<1, 1024, 30000*4 + 6000>>>(out);
}